// round 2
// baseline (speedup 1.0000x reference)
#include <cuda_runtime.h>

// Problem constants
#define D     768
#define T     8192
#define NREF  16384
#define C     96
#define KSEL  4

// GEMM tiling
#define TM    128
#define TN    128
#define KB    16
#define NSPLIT 2
#define CAND  64          // candidates per token per split (16 tx-threads * 4)

#define NEG_INF (-3.402823466e38f)

// ---- scratch (static device globals; no allocations allowed) ----
__device__ float g_inv_rnorm[NREF];                 // 64 KB
__device__ float g_P[C * NREF];                     // 6.3 MB : P = W @ lut
__device__ float g_cand_val[NSPLIT * T * CAND];     // 4 MB
__device__ int   g_cand_idx[NSPLIT * T * CAND];     // 4 MB

// ============================================================
// Kernel 1: inverse L2 norm of each reference column of lut [D, NREF]
// ============================================================
__global__ void norm_kernel(const float* __restrict__ lut) {
    int n = blockIdx.x * blockDim.x + threadIdx.x;
    if (n >= NREF) return;
    float s = 0.f;
#pragma unroll 8
    for (int d = 0; d < D; ++d) {
        float v = lut[d * NREF + n];
        s = fmaf(v, v, s);
    }
    g_inv_rnorm[n] = 1.0f / sqrtf(s);
}

// ============================================================
// Kernel 2: P[c][n] = sum_d W[c][d] * lut[d][n]   (96 x 16384 x 768)
// grid (NREF/128, C/4), block 128. Each thread: 1 column n, 4 channels.
// ============================================================
__global__ void proj_lut_kernel(const float* __restrict__ lut,
                                const float* __restrict__ w) {
    int n  = blockIdx.x * 128 + threadIdx.x;
    int c0 = blockIdx.y * 4;
    const float* w0 = w + (c0 + 0) * D;
    const float* w1 = w + (c0 + 1) * D;
    const float* w2 = w + (c0 + 2) * D;
    const float* w3 = w + (c0 + 3) * D;
    float a0 = 0.f, a1 = 0.f, a2 = 0.f, a3 = 0.f;
#pragma unroll 4
    for (int d = 0; d < D; ++d) {
        float l = lut[d * NREF + n];
        a0 = fmaf(w0[d], l, a0);
        a1 = fmaf(w1[d], l, a1);
        a2 = fmaf(w2[d], l, a2);
        a3 = fmaf(w3[d], l, a3);
    }
    g_P[(c0 + 0) * NREF + n] = a0;
    g_P[(c0 + 1) * NREF + n] = a1;
    g_P[(c0 + 2) * NREF + n] = a2;
    g_P[(c0 + 3) * NREF + n] = a3;
}

// ============================================================
// Kernel 3: fused GEMM + running top-4.
// score[t,n] = (sum_d x[d,t]*lut[d,n]) * inv_rnorm[n]
// grid: (NSPLIT, T/TM), block 256 (16x16), per-thread 8x8 C-tile.
// Per thread keeps top-4 per owned row across all N-tiles of its split;
// 64 candidates/token/split written to global for the merge kernel.
// ============================================================
__device__ __forceinline__ void insert4(float* v, int* ix, float s, int n) {
    if (s > v[3]) {
        if (s > v[0]) {
            v[3] = v[2]; ix[3] = ix[2];
            v[2] = v[1]; ix[2] = ix[1];
            v[1] = v[0]; ix[1] = ix[0];
            v[0] = s;    ix[0] = n;
        } else if (s > v[1]) {
            v[3] = v[2]; ix[3] = ix[2];
            v[2] = v[1]; ix[2] = ix[1];
            v[1] = s;    ix[1] = n;
        } else if (s > v[2]) {
            v[3] = v[2]; ix[3] = ix[2];
            v[2] = s;    ix[2] = n;
        } else {
            v[3] = s;    ix[3] = n;
        }
    }
}

__global__ __launch_bounds__(256, 1)
void match_kernel(const float* __restrict__ x, const float* __restrict__ lut) {
    __shared__ float As[KB][TM];
    __shared__ float Bs[KB][TN];
    __shared__ float Sn[TN];

    const int tid = threadIdx.x;
    const int tx  = tid & 15;
    const int ty  = tid >> 4;
    const int t0  = blockIdx.y * TM;
    const int nbeg = blockIdx.x * (NREF / NSPLIT);

    float topv[8][4];
    int   topi[8][4];
#pragma unroll
    for (int i = 0; i < 8; ++i)
#pragma unroll
        for (int j = 0; j < 4; ++j) { topv[i][j] = NEG_INF; topi[i][j] = 0; }

    const int NT = (NREF / NSPLIT) / TN;   // 64 n-tiles
    for (int nt = 0; nt < NT; ++nt) {
        const int n0 = nbeg + nt * TN;

        float acc[8][8];
#pragma unroll
        for (int i = 0; i < 8; ++i)
#pragma unroll
            for (int j = 0; j < 8; ++j) acc[i][j] = 0.f;

        if (tid < TN) Sn[tid] = g_inv_rnorm[n0 + tid];

        for (int kc = 0; kc < D / KB; ++kc) {
            const float* xp = x   + (kc * KB) * T    + t0;
            const float* lp = lut + (kc * KB) * NREF + n0;
#pragma unroll
            for (int i = 0; i < 8; ++i) {
                int e  = tid + i * 256;
                int kr = e >> 7;
                int cc = e & 127;
                As[kr][cc] = xp[kr * T + cc];
                Bs[kr][cc] = lp[kr * NREF + cc];
            }
            __syncthreads();

#pragma unroll
            for (int k = 0; k < KB; ++k) {
                float a[8], b[8];
                float4 v;
                v = *(const float4*)&As[k][ty * 4];
                a[0] = v.x; a[1] = v.y; a[2] = v.z; a[3] = v.w;
                v = *(const float4*)&As[k][64 + ty * 4];
                a[4] = v.x; a[5] = v.y; a[6] = v.z; a[7] = v.w;
                v = *(const float4*)&Bs[k][tx * 4];
                b[0] = v.x; b[1] = v.y; b[2] = v.z; b[3] = v.w;
                v = *(const float4*)&Bs[k][64 + tx * 4];
                b[4] = v.x; b[5] = v.y; b[6] = v.z; b[7] = v.w;
#pragma unroll
                for (int i = 0; i < 8; ++i)
#pragma unroll
                    for (int j = 0; j < 8; ++j)
                        acc[i][j] = fmaf(a[i], b[j], acc[i][j]);
            }
            __syncthreads();
        }

        // epilogue: scale by inv-norm, update running top-4 per row
        float sv[8];
        int   nn[8];
#pragma unroll
        for (int j = 0; j < 8; ++j) {
            int cl = tx * 4 + (j & 3) + ((j >> 2) * 64);
            sv[j] = Sn[cl];
            nn[j] = n0 + cl;
        }
#pragma unroll
        for (int i = 0; i < 8; ++i) {
#pragma unroll
            for (int j = 0; j < 8; ++j) {
                float s = acc[i][j] * sv[j];
                insert4(topv[i], topi[i], s, nn[j]);
            }
        }
        __syncthreads();   // protect Sn before next tile's reload
    }

    // write per-thread candidates (16 threads * 4 = 64 per token per split)
#pragma unroll
    for (int i = 0; i < 8; ++i) {
        int trow = t0 + ty * 4 + (i & 3) + ((i >> 2) * 64);
        int base = (blockIdx.x * T + trow) * CAND + tx * 4;
#pragma unroll
        for (int j = 0; j < 4; ++j) {
            g_cand_val[base + j] = topv[i][j];
            g_cand_idx[base + j] = topi[i][j];
        }
    }
}

// ============================================================
// Kernel 4: merge 128 candidates -> top-4, then
// out[c,t] = 0.25 * sum_k P[c, idx_k] + b[c]
// grid T blocks, 128 threads.
// ============================================================
__global__ void merge_project_kernel(const float* __restrict__ bias,
                                     float* __restrict__ out) {
    __shared__ float sv[NSPLIT * CAND];
    __shared__ int   si[NSPLIT * CAND];
    __shared__ int   sel[KSEL];

    const int t   = blockIdx.x;
    const int tid = threadIdx.x;

    const int split = tid >> 6;        // 0..1
    const int slot  = tid & 63;
    const int base  = (split * T + t) * CAND + slot;
    sv[tid] = g_cand_val[base];
    si[tid] = g_cand_idx[base];
    __syncthreads();

    if (tid == 0) {
        // serial top-4 selection with jax tie-break (lower index wins on ties)
        for (int j = 0; j < KSEL; ++j) {
            float bv = NEG_INF;
            int   bi = 0x7fffffff;
            int   bp = 0;
            for (int i = 0; i < NSPLIT * CAND; ++i) {
                float v = sv[i];
                int  ix = si[i];
                if (v > bv || (v == bv && ix < bi)) { bv = v; bi = ix; bp = i; }
            }
            sel[j] = bi;
            sv[bp] = NEG_INF;
        }
    }
    __syncthreads();

    if (tid < C) {
        const float* Pr = g_P + tid * NREF;
        float o = 0.25f * (Pr[sel[0]] + Pr[sel[1]] + Pr[sel[2]] + Pr[sel[3]]);
        out[tid * T + t] = o + bias[tid];
    }
}

// ============================================================
extern "C" void kernel_launch(void* const* d_in, const int* in_sizes, int n_in,
                              void* d_out, int out_size) {
    const float* x    = (const float*)d_in[0];   // [1, 768, 8192]
    const float* lut  = (const float*)d_in[1];   // [1, 768, 16384]
    const float* w    = (const float*)d_in[2];   // [96, 768]
    const float* bias = (const float*)d_in[3];   // [96]
    float* out = (float*)d_out;                  // [1, 96, 8192]

    norm_kernel<<<NREF / 256, 256>>>(lut);
    proj_lut_kernel<<<dim3(NREF / 128, C / 4), 128>>>(lut, w);
    match_kernel<<<dim3(NSPLIT, T / TM), 256>>>(x, lut);
    merge_project_kernel<<<T, 128>>>(bias, out);
}